// round 2
// baseline (speedup 1.0000x reference)
#include <cuda_runtime.h>
#include <string.h>

#define EPS 1e-5f

// ---------------- folded-weight scratch (device globals: allowed) ----------
__device__ __align__(16) float g_W1t[512 * 192];   // [c][j], j = k*64+o, BN1 scale folded
__device__ __align__(16) float g_b1f[192];         // BN1 folded bias
__device__ __align__(16) float g_W4t[64 * 512];    // [d][c], BN2 scale folded
__device__ __align__(16) float g_c4f[512];         // BN2 folded bias

// ---------------- prep: fold BN into weights ------------------------------
__global__ void prep_kernel(const float* __restrict__ W123, const float* __restrict__ b123,
                            const float* __restrict__ g123, const float* __restrict__ be123,
                            const float* __restrict__ m123, const float* __restrict__ v123,
                            const float* __restrict__ W4,   const float* __restrict__ b4,
                            const float* __restrict__ g4,   const float* __restrict__ be4,
                            const float* __restrict__ m4,   const float* __restrict__ v4)
{
    int idx = blockIdx.x * blockDim.x + threadIdx.x;
    if (idx < 512 * 192) {
        int c = idx / 192, j = idx % 192;
        float s = g123[j] * rsqrtf(v123[j] + EPS);
        g_W1t[c * 192 + j] = W123[j * 512 + c] * s;   // W123: (3,64,512) -> [j][c]
    }
    int i2 = idx - 512 * 192;
    if (i2 >= 0 && i2 < 192) {
        float s = g123[i2] * rsqrtf(v123[i2] + EPS);
        g_b1f[i2] = (b123[i2] - m123[i2]) * s + be123[i2];
    }
    int i3 = idx - (512 * 192 + 192);
    if (i3 >= 0 && i3 < 64 * 512) {
        int d = i3 / 512, c = i3 % 512;
        float s = g4[c] * rsqrtf(v4[c] + EPS);
        g_W4t[d * 512 + c] = W4[c * 64 + d] * s;      // W4: (512,64)
    }
    int i4 = idx - (512 * 192 + 192 + 64 * 512);
    if (i4 >= 0 && i4 < 512) {
        float s = g4[i4] * rsqrtf(v4[i4] + EPS);
        g_c4f[i4] = (b4[i4] - m4[i4]) * s + be4[i4];
    }
}

// ---------------- helpers --------------------------------------------------
__device__ __forceinline__ float2 ffma2(float2 a, float2 b, float2 c) {
    unsigned long long au, bu, cu, du;
    memcpy(&au, &a, 8); memcpy(&bu, &b, 8); memcpy(&cu, &c, 8);
    asm("fma.rn.f32x2 %0, %1, %2, %3;" : "=l"(du) : "l"(au), "l"(bu), "l"(cu));
    float2 d; memcpy(&d, &du, 8); return d;
}
__device__ __forceinline__ void cp_async16(float* smem_dst, const float* gsrc) {
    unsigned s = (unsigned)__cvta_generic_to_shared(smem_dst);
    asm volatile("cp.async.cg.shared.global [%0], [%1], 16;" :: "r"(s), "l"(gsrc));
}

// SMEM layout (floats):
//   sAT : [0, 34816)        A_T[512][68]  (k-major xs block; later reused as W4t[64][512])
//   sBS : [34816, 47104)    2 x 32 x 192  weight tiles (double buffer)
//   sATT: [47104, 51200)    att_s[16][64][4]
#define SM_TOTAL_FLOATS 51200

__global__ void __launch_bounds__(512, 1)
fused_kernel(const float* __restrict__ x, float* __restrict__ out)
{
    extern __shared__ float sm[];
    float* sAT  = sm;
    float* sBS  = sm + 34816;
    float* sATT = sm + 47104;

    const int t    = threadIdx.x;
    const int warp = t >> 5;        // 16 warps: warp <-> local sample
    const int g    = t & 31;        // lane: 2 channels per (q,k,v) group
    const int n0   = blockIdx.x * 16;

    // ---- Phase 0: gather xs (strided 2x2 slice) into A_T[k][row], row = 4*n_local + l
    {
        const float4* xb = (const float4*)x;
        #pragma unroll 4
        for (int i = 0; i < 16; i++) {
            long base = ((long)((n0 + i) * 512 + t)) * 4;   // float4 index of x[n][c] block
            float4 v0 = __ldg(&xb[base + 0]);               // h=0 row: w=0..3
            float4 v1 = __ldg(&xb[base + 2]);               // h=2 row: w=0..3
            *(float4*)&sAT[t * 68 + 4 * i] = make_float4(v0.x, v0.z, v1.x, v1.z);
        }
    }

    // ---- GEMM1 weight tile copier (tile = 32 k-rows x 192 cols, contiguous in g_W1t)
    auto copy_tile = [&](int kt, int buf) {
        const float* src = g_W1t + kt * 32 * 192;
        float* dst = sBS + buf * 6144;
        #pragma unroll
        for (int s = 0; s < 3; s++) {
            int q = t + s * 512;                 // 1536 float4 chunks
            cp_async16(dst + q * 4, src + q * 4);
        }
    };
    copy_tile(0, 0);
    asm volatile("cp.async.commit_group;");
    __syncthreads();   // A_T visible to all

    // ---- Phase 1: GEMM1  act[row 0..63][j 0..191] ; thread tile 4 rows x 6 cols (3 pairs)
    float2 acc[4][3];
    #pragma unroll
    for (int l = 0; l < 4; l++)
        #pragma unroll
        for (int p = 0; p < 3; p++) acc[l][p] = make_float2(0.f, 0.f);

    for (int kt = 0; kt < 16; kt++) {
        if (kt + 1 < 16) {
            copy_tile(kt + 1, (kt + 1) & 1);
            asm volatile("cp.async.commit_group;");
            asm volatile("cp.async.wait_group 1;");
        } else {
            asm volatile("cp.async.wait_group 0;");
        }
        __syncthreads();
        const float* bp = sBS + (kt & 1) * 6144;
        const float* ap = sAT + kt * 32 * 68 + 4 * warp;
        #pragma unroll 8
        for (int kk = 0; kk < 32; kk++) {
            float4 a  = *(const float4*)&ap[kk * 68];              // broadcast
            float2 b0 = *(const float2*)&bp[kk * 192 + 2 * g];        // q cols
            float2 b1 = *(const float2*)&bp[kk * 192 + 2 * g + 64];   // k cols
            float2 b2 = *(const float2*)&bp[kk * 192 + 2 * g + 128];  // v cols
            float2 a0 = make_float2(a.x, a.x), a1 = make_float2(a.y, a.y);
            float2 a2 = make_float2(a.z, a.z), a3 = make_float2(a.w, a.w);
            acc[0][0] = ffma2(a0, b0, acc[0][0]);
            acc[0][1] = ffma2(a0, b1, acc[0][1]);
            acc[0][2] = ffma2(a0, b2, acc[0][2]);
            acc[1][0] = ffma2(a1, b0, acc[1][0]);
            acc[1][1] = ffma2(a1, b1, acc[1][1]);
            acc[1][2] = ffma2(a1, b2, acc[1][2]);
            acc[2][0] = ffma2(a2, b0, acc[2][0]);
            acc[2][1] = ffma2(a2, b1, acc[2][1]);
            acc[2][2] = ffma2(a2, b2, acc[2][2]);
            acc[3][0] = ffma2(a3, b0, acc[3][0]);
            acc[3][1] = ffma2(a3, b1, acc[3][1]);
            acc[3][2] = ffma2(a3, b2, acc[3][2]);
        }
        __syncthreads();
    }

    // ---- folded BN bias + ReLU -> q2/k2/v2 for this warp's sample, lanes hold d=2g,2g+1
    float2 q2[4], k2[4], v2[4];
    {
        float2 bb0 = *(const float2*)&g_b1f[2 * g];
        float2 bb1 = *(const float2*)&g_b1f[2 * g + 64];
        float2 bb2 = *(const float2*)&g_b1f[2 * g + 128];
        #pragma unroll
        for (int l = 0; l < 4; l++) {
            q2[l].x = fmaxf(acc[l][0].x + bb0.x, 0.f);
            q2[l].y = fmaxf(acc[l][0].y + bb0.y, 0.f);
            k2[l].x = fmaxf(acc[l][1].x + bb1.x, 0.f);
            k2[l].y = fmaxf(acc[l][1].y + bb1.y, 0.f);
            v2[l].x = fmaxf(acc[l][2].x + bb2.x, 0.f);
            v2[l].y = fmaxf(acc[l][2].y + bb2.y, 0.f);
        }
    }

    // ---- start W4t copy into the (now dead) A_T region; overlaps with attention
    #pragma unroll
    for (int s = 0; s < 16; s++) {
        int q = t + s * 512;                       // 8192 float4 chunks
        cp_async16(sAT + q * 4, g_W4t + q * 4);
    }
    asm volatile("cp.async.commit_group;");

    // ---- Phase 2: warp-local attention (L=4), butterfly-reduce over 64 channels
    {
        float s[16];
        #pragma unroll
        for (int l = 0; l < 4; l++)
            #pragma unroll
            for (int m = 0; m < 4; m++)
                s[l * 4 + m] = q2[l].x * k2[m].x + q2[l].y * k2[m].y;
        #pragma unroll
        for (int off = 16; off > 0; off >>= 1)
            #pragma unroll
            for (int i = 0; i < 16; i++)
                s[i] += __shfl_xor_sync(0xffffffffu, s[i], off);

        float2 att2[4];
        #pragma unroll
        for (int l = 0; l < 4; l++) {
            float s0 = s[l * 4 + 0], s1 = s[l * 4 + 1], s2 = s[l * 4 + 2], s3 = s[l * 4 + 3];
            float mx = fmaxf(fmaxf(s0, s1), fmaxf(s2, s3));
            float e0 = __expf(s0 - mx), e1 = __expf(s1 - mx);
            float e2 = __expf(s2 - mx), e3 = __expf(s3 - mx);
            float inv = 1.f / (e0 + e1 + e2 + e3);
            att2[l].x = (e0 * v2[0].x + e1 * v2[1].x + e2 * v2[2].x + e3 * v2[3].x) * inv;
            att2[l].y = (e0 * v2[0].y + e1 * v2[1].y + e2 * v2[2].y + e3 * v2[3].y) * inv;
        }
        // att_s[n][d][l]: lane writes d=2g (x comps) and d=2g+1 (y comps)
        *(float4*)&sATT[warp * 256 + 8 * g]     = make_float4(att2[0].x, att2[1].x, att2[2].x, att2[3].x);
        *(float4*)&sATT[warp * 256 + 8 * g + 4] = make_float4(att2[0].y, att2[1].y, att2[2].y, att2[3].y);
    }

    asm volatile("cp.async.wait_group 0;");
    __syncthreads();   // W4t + att_s ready

    // ---- Phase 3: GEMM2  y[c][l] = sum_d att_s[n][d][l] * W4t[d][c]
    // lane handles c pairs {2g+64j, 2g+1+64j}, j=0..7
    float2 y[8][4];
    #pragma unroll
    for (int j = 0; j < 8; j++)
        #pragma unroll
        for (int l = 0; l < 4; l++) y[j][l] = make_float2(0.f, 0.f);

    const float* attn_row = &sATT[warp * 256];
    #pragma unroll 2
    for (int d = 0; d < 64; d++) {
        float4 a = *(const float4*)&attn_row[d * 4];   // broadcast att[d][0..3]
        float2 ap0 = make_float2(a.x, a.x), ap1 = make_float2(a.y, a.y);
        float2 ap2 = make_float2(a.z, a.z), ap3 = make_float2(a.w, a.w);
        const float* wr = &sAT[d * 512 + 2 * g];
        #pragma unroll
        for (int j = 0; j < 8; j++) {
            float2 w = *(const float2*)&wr[64 * j];
            y[j][0] = ffma2(ap0, w, y[j][0]);
            y[j][1] = ffma2(ap1, w, y[j][1]);
            y[j][2] = ffma2(ap2, w, y[j][2]);
            y[j][3] = ffma2(ap3, w, y[j][3]);
        }
    }

    // ---- Phase 4: residual epilogue: out[n,c,h,w] = x[n,c,h,w] + y[c][h] + c4[c]
    {
        long nbase = (long)(n0 + warp) * 512;
        #pragma unroll
        for (int j = 0; j < 8; j++) {
            int c0 = 2 * g + 64 * j;
            float2 cc = *(const float2*)&g_c4f[c0];
            const float4* xb4 = (const float4*)x + (nbase + c0) * 4;
            float4*       ob4 = (float4*)out    + (nbase + c0) * 4;
            #pragma unroll
            for (int l = 0; l < 4; l++) {
                float yv = y[j][l].x + cc.x;
                float4 v = __ldg(&xb4[l]);
                v.x += yv; v.y += yv; v.z += yv; v.w += yv;
                ob4[l] = v;
            }
            #pragma unroll
            for (int l = 0; l < 4; l++) {
                float yv = y[j][l].y + cc.y;
                float4 v = __ldg(&xb4[4 + l]);
                v.x += yv; v.y += yv; v.z += yv; v.w += yv;
                ob4[4 + l] = v;
            }
        }
    }
}

extern "C" void kernel_launch(void* const* d_in, const int* in_sizes, int n_in,
                              void* d_out, int out_size)
{
    const float* x    = (const float*)d_in[0];
    const float* W123 = (const float*)d_in[1];
    const float* b123 = (const float*)d_in[2];
    const float* g123 = (const float*)d_in[3];
    const float* be123= (const float*)d_in[4];
    const float* m123 = (const float*)d_in[5];
    const float* v123 = (const float*)d_in[6];
    const float* W4   = (const float*)d_in[7];
    const float* b4   = (const float*)d_in[8];
    const float* g4   = (const float*)d_in[9];
    const float* be4  = (const float*)d_in[10];
    const float* m4   = (const float*)d_in[11];
    const float* v4   = (const float*)d_in[12];

    int N = in_sizes[0] / (512 * 16);   // 2048

    prep_kernel<<<515, 256>>>(W123, b123, g123, be123, m123, v123,
                              W4, b4, g4, be4, m4, v4);

    cudaFuncSetAttribute(fused_kernel, cudaFuncAttributeMaxDynamicSharedMemorySize,
                         SM_TOTAL_FLOATS * 4);
    fused_kernel<<<N / 16, 512, SM_TOTAL_FLOATS * 4>>>(x, (float*)d_out);
}